// round 2
// baseline (speedup 1.0000x reference)
#include <cuda_runtime.h>
#include <cstddef>
#include <cstdint>

// Problem constants
#define BB    4
#define NBB   128
#define LQ    65
#define HH    8
#define HD    64
#define CC    512
#define NTOK  (BB * NBB * LQ)        // 33280
#define NBLK  (BB * NBB)             // 512
#define SCALE_F 0.125f               // HD^-0.5

// Scratch buffers (no cudaMalloc allowed; __device__ globals are the
// sanctioned mechanism per the harness rules)
__device__ float g_qkv[(size_t)NTOK * 1536];   // 204 MB
__device__ float g_att[(size_t)NTOK * 512];    //  68 MB

// ---------------------------------------------------------------------------
// SGEMM (NT): C[m][n] = sum_k A[m*K+k] * B[n*K+k] + bias[n]
// BM=BN=128, BK=8, 256 threads, 8x8 micro-tile (split 4+4 mapping).
// M % 128 == 0, N % 128 == 0, K % 8 == 0 guaranteed by problem shapes.
// ---------------------------------------------------------------------------
__global__ void __launch_bounds__(256, 2) sgemm_nt(
    const float* __restrict__ A, const float* __restrict__ Bm,
    const float* __restrict__ bias, float* __restrict__ C,
    int M, int N, int K)
{
    __shared__ float As[2][8][128];
    __shared__ float Bs[2][8][128];

    const int tid  = threadIdx.x;
    const int tx   = tid & 15;
    const int ty   = tid >> 4;
    const int bm   = blockIdx.y << 7;
    const int bn   = blockIdx.x << 7;
    const int arow = tid >> 1;
    const int ac   = (tid & 1) << 2;

    const float* Ap = A  + (size_t)(bm + arow) * K + ac;
    const float* Bp = Bm + (size_t)(bn + arow) * K + ac;

    float acc[8][8];
#pragma unroll
    for (int i = 0; i < 8; i++)
#pragma unroll
        for (int j = 0; j < 8; j++) acc[i][j] = 0.f;

    // prologue: stage k-slab 0
    float4 a = *(const float4*)Ap;
    float4 b = *(const float4*)Bp;
    As[0][ac+0][arow] = a.x; As[0][ac+1][arow] = a.y;
    As[0][ac+2][arow] = a.z; As[0][ac+3][arow] = a.w;
    Bs[0][ac+0][arow] = b.x; Bs[0][ac+1][arow] = b.y;
    Bs[0][ac+2][arow] = b.z; Bs[0][ac+3][arow] = b.w;
    __syncthreads();

    const int nk = K >> 3;
    int buf = 0;
    for (int t = 1; t <= nk; t++) {
        if (t < nk) {
            a = *(const float4*)(Ap + (t << 3));
            b = *(const float4*)(Bp + (t << 3));
        }
#pragma unroll
        for (int kk = 0; kk < 8; kk++) {
            float af[8], bf[8];
#pragma unroll
            for (int i = 0; i < 4; i++) {
                af[i]     = As[buf][kk][ty * 4 + i];
                af[4 + i] = As[buf][kk][64 + ty * 4 + i];
                bf[i]     = Bs[buf][kk][tx * 4 + i];
                bf[4 + i] = Bs[buf][kk][64 + tx * 4 + i];
            }
#pragma unroll
            for (int i = 0; i < 8; i++)
#pragma unroll
                for (int j = 0; j < 8; j++)
                    acc[i][j] += af[i] * bf[j];
        }
        if (t < nk) {
            buf ^= 1;
            As[buf][ac+0][arow] = a.x; As[buf][ac+1][arow] = a.y;
            As[buf][ac+2][arow] = a.z; As[buf][ac+3][arow] = a.w;
            Bs[buf][ac+0][arow] = b.x; Bs[buf][ac+1][arow] = b.y;
            Bs[buf][ac+2][arow] = b.z; Bs[buf][ac+3][arow] = b.w;
            __syncthreads();
        }
    }

    // epilogue
    float bb[8];
#pragma unroll
    for (int j = 0; j < 4; j++) {
        bb[j]     = bias[bn + tx * 4 + j];
        bb[4 + j] = bias[bn + 64 + tx * 4 + j];
    }
#pragma unroll
    for (int i = 0; i < 8; i++) {
        int row = bm + ((i < 4) ? (ty * 4 + i) : (64 + ty * 4 + (i - 4)));
        float* Cp = C + (size_t)row * N + bn;
        float4 v0 = make_float4(acc[i][0] + bb[0], acc[i][1] + bb[1],
                                acc[i][2] + bb[2], acc[i][3] + bb[3]);
        float4 v1 = make_float4(acc[i][4] + bb[4], acc[i][5] + bb[5],
                                acc[i][6] + bb[6], acc[i][7] + bb[7]);
        *(float4*)(Cp + tx * 4)      = v0;
        *(float4*)(Cp + 64 + tx * 4) = v1;
    }
}

// ---------------------------------------------------------------------------
// Fused block attention. One CTA per (block, head): 4096 CTAs, 128 threads.
// smem: Q(65x64) K(65 rows, stride 68) V(65x64) bias3(65x65) gate(65x65)
//       + per-warp combined-score buffers (4 rows x 68)
// Each warp processes 4 q-rows at a time; keys split as {lane, lane+32, 64}.
// Mask folded into bias3 (-1e30) / gate (0).
// ---------------------------------------------------------------------------
#define SMEM_FLOATS (4160 + 65*68 + 4160 + 4225 + 4225 + 4*4*68)

__global__ void __launch_bounds__(128) attn_kernel(
    const float* __restrict__ qkv, const int* __restrict__ mask,
    const float* __restrict__ edge, const float* __restrict__ gate_w,
    const float* __restrict__ gate_b, float* __restrict__ outp)
{
    extern __shared__ float sm[];
    float* sQ  = sm;                         // 4160
    float* sK  = sm + 4160;                  // 65*68 = 4420 (stride 68)
    float* sV  = sm + 4160 + 4420;           // 4160
    float* sB3 = sm + 4160 + 4420 + 4160;    // 4225
    float* sG  = sB3 + 4225;                 // 4225
    float* sS  = sG + 4225;                  // 4 warps * 4 rows * 68

    const int blk  = blockIdx.x >> 3;
    const int h    = blockIdx.x & 7;
    const int tid  = threadIdx.x;
    const int lane = tid & 31;
    const int warp = tid >> 5;

    // ---- stage Q/K/V for this head ----
    const float* qb = qkv + (size_t)blk * (LQ * 1536) + h * 64;
    for (int i = tid; i < LQ * 16; i += 128) {
        int l = i >> 4, c = (i & 15) << 2;
        const float* p = qb + (size_t)l * 1536 + c;
        float4 qv = *(const float4*)(p);
        float4 kv = *(const float4*)(p + 512);
        float4 vv = *(const float4*)(p + 1024);
        *(float4*)(sQ + l * 64 + c) = qv;
        sK[l * 68 + c + 0] = kv.x; sK[l * 68 + c + 1] = kv.y;
        sK[l * 68 + c + 2] = kv.z; sK[l * 68 + c + 3] = kv.w;
        *(float4*)(sV + l * 64 + c) = vv;
    }

    // ---- stage bias3 / gate with diag override + mask folding ----
    const float gw0 = gate_w[h * 4 + 0], gw1 = gate_w[h * 4 + 1];
    const float gw2 = gate_w[h * 4 + 2], gw3 = gate_w[h * 4 + 3];
    const float gb  = gate_b[h];
    const float* eb = edge + (size_t)blk * (LQ * LQ * 4);
    const int*   mb = mask + (size_t)blk * (LQ * LQ);
    for (int i = tid; i < LQ * LQ; i += 128) {
        int qr = i / 65, kc = i - qr * 65;
        float4 e = *(const float4*)(eb + (size_t)i * 4);
        if (qr == kc && qr < 64) { e.x = 0.f; e.y = 0.f; e.z = 0.f; e.w = 1.f; }
        float g  = e.x * gw0 + e.y * gw1 + e.z * gw2 + e.w * gw3 + gb;
        float b3 = e.w;
        if (mb[i] == 0) { g = 0.f; b3 = -1e30f; }
        sB3[i] = b3;
        sG[i]  = g;
    }
    __syncthreads();

    float* myS = sS + warp * (4 * 68);

    for (int base = warp * 4; base < 65; base += 16) {
        const int nr = (65 - base) < 4 ? (65 - base) : 4;
        const float* q0 = sQ + base * 64;

        // scores: keys {lane, lane+32} x 4 rows, register-blocked
        float acc0[4] = {0.f, 0.f, 0.f, 0.f};
        float acc1[4] = {0.f, 0.f, 0.f, 0.f};
        const float* kr1 = sK + lane * 68;
        const float* kr2 = sK + (lane + 32) * 68;
#pragma unroll
        for (int d = 0; d < 64; d += 4) {
            float4 k1 = *(const float4*)(kr1 + d);
            float4 k2 = *(const float4*)(kr2 + d);
#pragma unroll
            for (int i = 0; i < 4; i++) {
                float4 qv = *(const float4*)(q0 + i * 64 + d);
                acc0[i] += qv.x * k1.x + qv.y * k1.y + qv.z * k1.z + qv.w * k1.w;
                acc1[i] += qv.x * k2.x + qv.y * k2.y + qv.z * k2.z + qv.w * k2.w;
            }
        }
        // key 64 via cross-lane reduction
        float s64[4];
        {
            const float* k64 = sK + 64 * 68;
            float ka = k64[lane], kb = k64[lane + 32];
#pragma unroll
            for (int i = 0; i < 4; i++) {
                float p = q0[i * 64 + lane] * ka + q0[i * 64 + lane + 32] * kb;
#pragma unroll
                for (int o = 16; o; o >>= 1) p += __shfl_xor_sync(0xffffffffu, p, o);
                s64[i] = p;
            }
        }

        // softmax + gate (per valid row; nr is warp-uniform)
#pragma unroll
        for (int i = 0; i < 4; i++) {
            if (i >= nr) break;
            const int r = base + i;
            const float* brow = sB3 + r * 65;
            const float* grow = sG  + r * 65;
            float sc0 = acc0[i] * SCALE_F + brow[lane];
            float sc1 = acc1[i] * SCALE_F + brow[lane + 32];
            float sc2 = s64[i]  * SCALE_F + brow[64];
            float m = fmaxf(sc2, fmaxf(sc0, sc1));
#pragma unroll
            for (int o = 16; o; o >>= 1) m = fmaxf(m, __shfl_xor_sync(0xffffffffu, m, o));
            float p0 = __expf(sc0 - m), p1 = __expf(sc1 - m), p2 = __expf(sc2 - m);
            float s = p0 + p1;
#pragma unroll
            for (int o = 16; o; o >>= 1) s += __shfl_xor_sync(0xffffffffu, s, o);
            float inv = 1.f / (s + p2);
            myS[i * 68 + lane]      = p0 * inv + grow[lane];
            myS[i * 68 + lane + 32] = p1 * inv + grow[lane + 32];
            if (lane == 0) myS[i * 68 + 64] = p2 * inv + grow[64];
        }
        __syncwarp();

        // out = combined @ V, register-blocked over 4 rows
        float o0[4] = {0.f, 0.f, 0.f, 0.f};
        float o1[4] = {0.f, 0.f, 0.f, 0.f};
        for (int k = 0; k < 65; k++) {
            float v0 = sV[k * 64 + lane];
            float v1 = sV[k * 64 + lane + 32];
#pragma unroll
            for (int i = 0; i < 4; i++) {
                float c = myS[i * 68 + k];
                o0[i] += c * v0;
                o1[i] += c * v1;
            }
        }
#pragma unroll
        for (int i = 0; i < 4; i++) {
            if (i < nr) {
                float* op = outp + ((size_t)(blk * 65 + base + i)) * 512 + h * 64;
                op[lane]      = o0[i];
                op[lane + 32] = o1[i];
            }
        }
        __syncwarp();
    }
}

// ---------------------------------------------------------------------------
extern "C" void kernel_launch(void* const* d_in, const int* in_sizes, int n_in,
                              void* d_out, int out_size)
{
    const float* x         = (const float*)d_in[0];
    const int*   attn_mask = (const int*)  d_in[1];
    const float* edge      = (const float*)d_in[2];
    const float* qkv_w     = (const float*)d_in[3];
    const float* qkv_b     = (const float*)d_in[4];
    const float* proj_w    = (const float*)d_in[5];
    const float* proj_b    = (const float*)d_in[6];
    const float* gate_w    = (const float*)d_in[7];
    const float* gate_b    = (const float*)d_in[8];
    float* out = (float*)d_out;

    float *qkv = nullptr, *att = nullptr;
    cudaGetSymbolAddress((void**)&qkv, g_qkv);
    cudaGetSymbolAddress((void**)&att, g_att);

    const int smem_bytes = SMEM_FLOATS * (int)sizeof(float);
    cudaFuncSetAttribute(attn_kernel,
                         cudaFuncAttributeMaxDynamicSharedMemorySize, smem_bytes);

    // 1) QKV projection: (33280 x 512) @ (1536 x 512)^T
    dim3 g1(1536 / 128, NTOK / 128);
    sgemm_nt<<<g1, 256>>>(x, qkv_w, qkv_b, qkv, NTOK, 1536, 512);

    // 2) Fused block attention (bias + mask + softmax + gate + PV)
    attn_kernel<<<NBLK * HH, 128, smem_bytes>>>(qkv, attn_mask, edge,
                                                gate_w, gate_b, att);

    // 3) Output projection: (33280 x 512) @ (512 x 512)^T
    dim3 g2(512 / 128, NTOK / 128);
    sgemm_nt<<<g2, 256>>>(att, proj_w, proj_b, out, NTOK, 512, 512);
}

// round 7
// speedup vs baseline: 1.6435x; 1.6435x over previous
#include <cuda_runtime.h>
#include <cuda_bf16.h>
#include <cstddef>
#include <cstdint>

// Problem constants
#define BB    4
#define NBB   128
#define LQ    65
#define HH    8
#define HD    64
#define CC    512
#define NTOK  (BB * NBB * LQ)        // 33280
#define NBLK  (BB * NBB)             // 512
#define SCALE_F 0.125f               // HD^-0.5

// Scratch (no cudaMalloc allowed)
__device__ float         g_qkv[(size_t)NTOK * 1536];     // 204 MB (f32, attention input)
__device__ __nv_bfloat16 g_xhi[(size_t)NTOK * 512];
__device__ __nv_bfloat16 g_xlo[(size_t)NTOK * 512];
__device__ __nv_bfloat16 g_wqhi[1536 * 512];
__device__ __nv_bfloat16 g_wqlo[1536 * 512];
__device__ __nv_bfloat16 g_wphi[512 * 512];
__device__ __nv_bfloat16 g_wplo[512 * 512];
__device__ __nv_bfloat16 g_ahi[(size_t)NTOK * 512];      // attention out hi
__device__ __nv_bfloat16 g_alo[(size_t)NTOK * 512];      // attention out lo

// ===========================================================================
// helpers
// ===========================================================================
__device__ __forceinline__ uint32_t smem_u32(const void* p) {
    uint32_t a;
    asm("{ .reg .u64 t; cvta.to.shared.u64 t, %1; cvt.u32.u64 %0, t; }"
        : "=r"(a) : "l"(p));
    return a;
}

__device__ __forceinline__ void cp_async16(uint32_t saddr, const void* gaddr) {
    asm volatile("cp.async.cg.shared.global [%0], [%1], 16;"
                 :: "r"(saddr), "l"(gaddr));
}

__device__ __forceinline__ void ldm4(uint32_t* r, uint32_t addr) {
    asm volatile("ldmatrix.sync.aligned.m8n8.x4.shared.b16 {%0,%1,%2,%3}, [%4];"
                 : "=r"(r[0]), "=r"(r[1]), "=r"(r[2]), "=r"(r[3]) : "r"(addr));
}

__device__ __forceinline__ void mma_bf16(float* d, const uint32_t* a,
                                         const uint32_t* b) {
    asm volatile(
        "mma.sync.aligned.m16n8k16.row.col.f32.bf16.bf16.f32 "
        "{%0,%1,%2,%3}, {%4,%5,%6,%7}, {%8,%9}, {%0,%1,%2,%3};"
        : "+f"(d[0]), "+f"(d[1]), "+f"(d[2]), "+f"(d[3])
        : "r"(a[0]), "r"(a[1]), "r"(a[2]), "r"(a[3]), "r"(b[0]), "r"(b[1]));
}

// ===========================================================================
// f32 -> (bf16 hi, bf16 lo) splitter.  total elems divisible by 4*256*grid.
// ===========================================================================
__global__ void split_bf16(const float* __restrict__ in,
                           __nv_bfloat16* __restrict__ hi,
                           __nv_bfloat16* __restrict__ lo) {
    const int i = blockIdx.x * blockDim.x + threadIdx.x;
    float4 v = ((const float4*)in)[i];
    __nv_bfloat16 h0 = __float2bfloat16(v.x);
    __nv_bfloat16 h1 = __float2bfloat16(v.y);
    __nv_bfloat16 h2 = __float2bfloat16(v.z);
    __nv_bfloat16 h3 = __float2bfloat16(v.w);
    __nv_bfloat16 l0 = __float2bfloat16(v.x - __bfloat162float(h0));
    __nv_bfloat16 l1 = __float2bfloat16(v.y - __bfloat162float(h1));
    __nv_bfloat16 l2 = __float2bfloat16(v.z - __bfloat162float(h2));
    __nv_bfloat16 l3 = __float2bfloat16(v.w - __bfloat162float(h3));
    ((__nv_bfloat162*)hi)[2 * i]     = __halves2bfloat162(h0, h1);
    ((__nv_bfloat162*)hi)[2 * i + 1] = __halves2bfloat162(h2, h3);
    ((__nv_bfloat162*)lo)[2 * i]     = __halves2bfloat162(l0, l1);
    ((__nv_bfloat162*)lo)[2 * i + 1] = __halves2bfloat162(l2, l3);
}

// ===========================================================================
// bf16x3 tensor-core GEMM (NT): C[m][n] = sum_k A[m][k]*B[n][k] + bias[n]
//   A = Ahi + Alo, B = Bhi + Blo; D += AhBh + AhBl + AlBh   (fp32 accum)
// BM=BN=128, BK=32, 256 thr (8 warps: warp_m in {0,1} x warp_n in {0..3},
// warp tile 64x32). cp.async 3-stage pipeline. smem rows padded to 80B
// (row-stride 5 quad-banks -> conflict-free ldmatrix).
// M%128==0, N%128==0, K%32==0.
// ===========================================================================
#define PB      10240                // plane bytes: 128 rows * 80B
#define STAGE_B (4 * PB)             // Ahi,Alo,Bhi,Blo
#define STAGES  3
#define GEMM_SMEM (STAGES * STAGE_B) // 122880

__global__ void __launch_bounds__(256) gemm_bf16x3(
    const __nv_bfloat16* __restrict__ Ah, const __nv_bfloat16* __restrict__ Al,
    const __nv_bfloat16* __restrict__ Bh, const __nv_bfloat16* __restrict__ Bl,
    const float* __restrict__ bias, float* __restrict__ C,
    int M, int N, int K)
{
    extern __shared__ char smem[];
    const uint32_t sb = smem_u32(smem);
    const int tid    = threadIdx.x;
    const int lane   = tid & 31;
    const int wid    = tid >> 5;
    const int warp_m = wid & 1;
    const int warp_n = wid >> 1;
    const int bm     = blockIdx.y << 7;
    const int bn     = blockIdx.x << 7;

    // ---- cp.async mapping: 8 x 16B per thread per stage ----
    uint32_t s_off[8];
    const __nv_bfloat16* g_ptr[8];
#pragma unroll
    for (int i = 0; i < 8; i++) {
        const int c   = tid + (i << 8);     // 0..2047
        const int p   = c >> 9;             // plane
        const int q   = c & 511;
        const int row = q >> 2;
        const int seg = q & 3;
        s_off[i] = p * PB + row * 80 + seg * 16;
        const __nv_bfloat16* base =
            (p == 0) ? Ah + (size_t)(bm + row) * K :
            (p == 1) ? Al + (size_t)(bm + row) * K :
            (p == 2) ? Bh + (size_t)(bn + row) * K :
                       Bl + (size_t)(bn + row) * K;
        g_ptr[i] = base + seg * 8;
    }

    auto issue = [&](int s, int t) {
        const uint32_t sbase = sb + s * STAGE_B;
#pragma unroll
        for (int i = 0; i < 8; i++)
            cp_async16(sbase + s_off[i], g_ptr[i] + t * 32);
        asm volatile("cp.async.commit_group;");
    };

    float d[4][4][4];
#pragma unroll
    for (int mi = 0; mi < 4; mi++)
#pragma unroll
        for (int ni = 0; ni < 4; ni++)
#pragma unroll
            for (int j = 0; j < 4; j++) d[mi][ni][j] = 0.f;

    // per-lane ldmatrix bases (bytes within plane)
    const uint32_t a_base = (warp_m * 64 + (lane & 15)) * 80 + (lane >> 4) * 16;
    const uint32_t b_base = (warp_n * 32 + (lane & 7) + ((lane >> 4) & 1) * 8) * 80
                          + ((lane >> 3) & 1) * 16;

    const int nchunk = K >> 5;
    issue(0, 0);
    issue(1, 1);

    for (int t = 0; t < nchunk; t++) {
        if (t < nchunk - 1) asm volatile("cp.async.wait_group 1;");
        else                asm volatile("cp.async.wait_group 0;");
        __syncthreads();

        const uint32_t st = sb + (t % STAGES) * STAGE_B;
        const uint32_t aH = st, aL = st + PB, bH = st + 2 * PB, bL = st + 3 * PB;
#pragma unroll
        for (int ks = 0; ks < 2; ks++) {
            uint32_t ah[4][4], al[4][4], bh[4][2], bl[4][2];
            const uint32_t ka = a_base + ks * 32;
            const uint32_t kb = b_base + ks * 32;
#pragma unroll
            for (int mi = 0; mi < 4; mi++) {
                ldm4(ah[mi], aH + ka + mi * 1280);
                ldm4(al[mi], aL + ka + mi * 1280);
            }
#pragma unroll
            for (int nj = 0; nj < 2; nj++) {
                uint32_t r[4];
                ldm4(r, bH + kb + nj * 1280);
                bh[2*nj][0] = r[0]; bh[2*nj][1] = r[1];
                bh[2*nj+1][0] = r[2]; bh[2*nj+1][1] = r[3];
                ldm4(r, bL + kb + nj * 1280);
                bl[2*nj][0] = r[0]; bl[2*nj][1] = r[1];
                bl[2*nj+1][0] = r[2]; bl[2*nj+1][1] = r[3];
            }
#pragma unroll
            for (int mi = 0; mi < 4; mi++)
#pragma unroll
                for (int ni = 0; ni < 4; ni++) {
                    mma_bf16(d[mi][ni], ah[mi], bh[ni]);
                    mma_bf16(d[mi][ni], ah[mi], bl[ni]);
                    mma_bf16(d[mi][ni], al[mi], bh[ni]);
                }
        }
        __syncthreads();
        if (t + STAGES - 1 < nchunk) issue((t + STAGES - 1) % STAGES, t + STAGES - 1);
    }

    // ---- epilogue ----
#pragma unroll
    for (int ni = 0; ni < 4; ni++) {
        const int cn = bn + warp_n * 32 + ni * 8 + 2 * (lane & 3);
        const float b0 = bias[cn], b1 = bias[cn + 1];
#pragma unroll
        for (int mi = 0; mi < 4; mi++) {
            const int r0 = bm + warp_m * 64 + mi * 16 + (lane >> 2);
            float2 v0 = make_float2(d[mi][ni][0] + b0, d[mi][ni][1] + b1);
            float2 v1 = make_float2(d[mi][ni][2] + b0, d[mi][ni][3] + b1);
            *(float2*)(C + (size_t)r0 * N + cn)       = v0;
            *(float2*)(C + (size_t)(r0 + 8) * N + cn) = v1;
        }
    }
}

// ---------------------------------------------------------------------------
// Fused block attention (same math as passing R2 version); output emitted
// as bf16 hi/lo planes for the proj GEMM.
// ---------------------------------------------------------------------------
#define SMEM_FLOATS (4160 + 65*68 + 4160 + 4225 + 4225 + 4*4*68)

__global__ void __launch_bounds__(128) attn_kernel(
    const float* __restrict__ qkv, const int* __restrict__ mask,
    const float* __restrict__ edge, const float* __restrict__ gate_w,
    const float* __restrict__ gate_b,
    __nv_bfloat16* __restrict__ ohi, __nv_bfloat16* __restrict__ olo)
{
    extern __shared__ float sm[];
    float* sQ  = sm;
    float* sK  = sm + 4160;
    float* sV  = sm + 4160 + 4420;
    float* sB3 = sm + 4160 + 4420 + 4160;
    float* sG  = sB3 + 4225;
    float* sS  = sG + 4225;

    const int blk  = blockIdx.x >> 3;
    const int h    = blockIdx.x & 7;
    const int tid  = threadIdx.x;
    const int lane = tid & 31;
    const int warp = tid >> 5;

    const float* qb = qkv + (size_t)blk * (LQ * 1536) + h * 64;
    for (int i = tid; i < LQ * 16; i += 128) {
        int l = i >> 4, c = (i & 15) << 2;
        const float* p = qb + (size_t)l * 1536 + c;
        float4 qv = *(const float4*)(p);
        float4 kv = *(const float4*)(p + 512);
        float4 vv = *(const float4*)(p + 1024);
        *(float4*)(sQ + l * 64 + c) = qv;
        sK[l * 68 + c + 0] = kv.x; sK[l * 68 + c + 1] = kv.y;
        sK[l * 68 + c + 2] = kv.z; sK[l * 68 + c + 3] = kv.w;
        *(float4*)(sV + l * 64 + c) = vv;
    }

    const float gw0 = gate_w[h * 4 + 0], gw1 = gate_w[h * 4 + 1];
    const float gw2 = gate_w[h * 4 + 2], gw3 = gate_w[h * 4 + 3];
    const float gb  = gate_b[h];
    const float* eb = edge + (size_t)blk * (LQ * LQ * 4);
    const int*   mb = mask + (size_t)blk * (LQ * LQ);
    for (int i = tid; i < LQ * LQ; i += 128) {
        int qr = i / 65, kc = i - qr * 65;
        float4 e = *(const float4*)(eb + (size_t)i * 4);
        if (qr == kc && qr < 64) { e.x = 0.f; e.y = 0.f; e.z = 0.f; e.w = 1.f; }
        float g  = e.x * gw0 + e.y * gw1 + e.z * gw2 + e.w * gw3 + gb;
        float b3 = e.w;
        if (mb[i] == 0) { g = 0.f; b3 = -1e30f; }
        sB3[i] = b3;
        sG[i]  = g;
    }
    __syncthreads();

    float* myS = sS + warp * (4 * 68);

    for (int base = warp * 4; base < 65; base += 16) {
        const int nr = (65 - base) < 4 ? (65 - base) : 4;
        const float* q0 = sQ + base * 64;

        float acc0[4] = {0.f, 0.f, 0.f, 0.f};
        float acc1[4] = {0.f, 0.f, 0.f, 0.f};
        const float* kr1 = sK + lane * 68;
        const float* kr2 = sK + (lane + 32) * 68;
#pragma unroll
        for (int d = 0; d < 64; d += 4) {
            float4 k1 = *(const float4*)(kr1 + d);
            float4 k2 = *(const float4*)(kr2 + d);
#pragma unroll
            for (int i = 0; i < 4; i++) {
                float4 qv = *(const float4*)(q0 + i * 64 + d);
                acc0[i] += qv.x * k1.x + qv.y * k1.y + qv.z * k1.z + qv.w * k1.w;
                acc1[i] += qv.x * k2.x + qv.y * k2.y + qv.z * k2.z + qv.w * k2.w;
            }
        }
        float s64[4];
        {
            const float* k64 = sK + 64 * 68;
            float ka = k64[lane], kb = k64[lane + 32];
#pragma unroll
            for (int i = 0; i < 4; i++) {
                float p = q0[i * 64 + lane] * ka + q0[i * 64 + lane + 32] * kb;
#pragma unroll
                for (int o = 16; o; o >>= 1) p += __shfl_xor_sync(0xffffffffu, p, o);
                s64[i] = p;
            }
        }

#pragma unroll
        for (int i = 0; i < 4; i++) {
            if (i >= nr) break;
            const int r = base + i;
            const float* brow = sB3 + r * 65;
            const float* grow = sG  + r * 65;
            float sc0 = acc0[i] * SCALE_F + brow[lane];
            float sc1 = acc1[i] * SCALE_F + brow[lane + 32];
            float sc2 = s64[i]  * SCALE_F + brow[64];
            float m = fmaxf(sc2, fmaxf(sc0, sc1));
#pragma unroll
            for (int o = 16; o; o >>= 1) m = fmaxf(m, __shfl_xor_sync(0xffffffffu, m, o));
            float p0 = __expf(sc0 - m), p1 = __expf(sc1 - m), p2 = __expf(sc2 - m);
            float s = p0 + p1;
#pragma unroll
            for (int o = 16; o; o >>= 1) s += __shfl_xor_sync(0xffffffffu, s, o);
            float inv = 1.f / (s + p2);
            myS[i * 68 + lane]      = p0 * inv + grow[lane];
            myS[i * 68 + lane + 32] = p1 * inv + grow[lane + 32];
            if (lane == 0) myS[i * 68 + 64] = p2 * inv + grow[64];
        }
        __syncwarp();

        float o0[4] = {0.f, 0.f, 0.f, 0.f};
        float o1[4] = {0.f, 0.f, 0.f, 0.f};
        for (int k = 0; k < 65; k++) {
            float v0 = sV[k * 64 + lane];
            float v1 = sV[k * 64 + lane + 32];
#pragma unroll
            for (int i = 0; i < 4; i++) {
                float c = myS[i * 68 + k];
                o0[i] += c * v0;
                o1[i] += c * v1;
            }
        }
#pragma unroll
        for (int i = 0; i < 4; i++) {
            if (i < nr) {
                const size_t idx = ((size_t)(blk * 65 + base + i)) * 512 + h * 64;
                float va = o0[i], vb = o1[i];
                __nv_bfloat16 ha = __float2bfloat16(va);
                __nv_bfloat16 hb = __float2bfloat16(vb);
                ohi[idx + lane]      = ha;
                ohi[idx + lane + 32] = hb;
                olo[idx + lane]      = __float2bfloat16(va - __bfloat162float(ha));
                olo[idx + lane + 32] = __float2bfloat16(vb - __bfloat162float(hb));
            }
        }
        __syncwarp();
    }
}

// ---------------------------------------------------------------------------
extern "C" void kernel_launch(void* const* d_in, const int* in_sizes, int n_in,
                              void* d_out, int out_size)
{
    const float* x         = (const float*)d_in[0];
    const int*   attn_mask = (const int*)  d_in[1];
    const float* edge      = (const float*)d_in[2];
    const float* qkv_w     = (const float*)d_in[3];
    const float* qkv_b     = (const float*)d_in[4];
    const float* proj_w    = (const float*)d_in[5];
    const float* proj_b    = (const float*)d_in[6];
    const float* gate_w    = (const float*)d_in[7];
    const float* gate_b    = (const float*)d_in[8];
    float* out = (float*)d_out;

    float *qkv = nullptr;
    __nv_bfloat16 *xhi, *xlo, *wqhi, *wqlo, *wphi, *wplo, *ahi, *alo;
    cudaGetSymbolAddress((void**)&qkv,  g_qkv);
    cudaGetSymbolAddress((void**)&xhi,  g_xhi);
    cudaGetSymbolAddress((void**)&xlo,  g_xlo);
    cudaGetSymbolAddress((void**)&wqhi, g_wqhi);
    cudaGetSymbolAddress((void**)&wqlo, g_wqlo);
    cudaGetSymbolAddress((void**)&wphi, g_wphi);
    cudaGetSymbolAddress((void**)&wplo, g_wplo);
    cudaGetSymbolAddress((void**)&ahi,  g_ahi);
    cudaGetSymbolAddress((void**)&alo,  g_alo);

    cudaFuncSetAttribute(gemm_bf16x3,
                         cudaFuncAttributeMaxDynamicSharedMemorySize, GEMM_SMEM);
    const int attn_smem = SMEM_FLOATS * (int)sizeof(float);
    cudaFuncSetAttribute(attn_kernel,
                         cudaFuncAttributeMaxDynamicSharedMemorySize, attn_smem);

    // 0) split inputs/weights into bf16 hi/lo planes
    split_bf16<<<(NTOK * 512) / 1024, 256>>>(x, xhi, xlo);
    split_bf16<<<(1536 * 512) / 1024, 256>>>(qkv_w, wqhi, wqlo);
    split_bf16<<<(512 * 512) / 1024, 256>>>(proj_w, wphi, wplo);

    // 1) QKV projection (bf16x3 tensor cores)
    dim3 g1(1536 / 128, NTOK / 128);
    gemm_bf16x3<<<g1, 256, GEMM_SMEM>>>(xhi, xlo, wqhi, wqlo, qkv_b, qkv,
                                        NTOK, 1536, 512);

    // 2) Fused block attention (f32 in, bf16 hi/lo out)
    attn_kernel<<<NBLK * HH, 128, attn_smem>>>(qkv, attn_mask, edge,
                                               gate_w, gate_b, ahi, alo);

    // 3) Output projection (bf16x3 tensor cores)
    dim3 g2(512 / 128, NTOK / 128);
    gemm_bf16x3<<<g2, 256, GEMM_SMEM>>>(ahi, alo, wphi, wplo, proj_b, out,
                                        NTOK, 512, 512);
}

// round 9
// speedup vs baseline: 1.8673x; 1.1362x over previous
#include <cuda_runtime.h>
#include <cuda_bf16.h>
#include <cstddef>
#include <cstdint>

// Problem constants
#define BB    4
#define NBB   128
#define LQ    65
#define HH    8
#define HD    64
#define CC    512
#define NTOK  (BB * NBB * LQ)        // 33280
#define NBLK  (BB * NBB)             // 512
#define SCALE_F 0.125f               // HD^-0.5

// Scratch (no cudaMalloc allowed)
__device__ float         g_qkv[(size_t)NTOK * 1536];     // 204 MB (f32, attention input)
__device__ __nv_bfloat16 g_xhi[(size_t)NTOK * 512];
__device__ __nv_bfloat16 g_xlo[(size_t)NTOK * 512];
__device__ __nv_bfloat16 g_wqhi[1536 * 512];
__device__ __nv_bfloat16 g_wqlo[1536 * 512];
__device__ __nv_bfloat16 g_wphi[512 * 512];
__device__ __nv_bfloat16 g_wplo[512 * 512];
__device__ __nv_bfloat16 g_ahi[(size_t)NTOK * 512];      // attention out hi
__device__ __nv_bfloat16 g_alo[(size_t)NTOK * 512];      // attention out lo

// ===========================================================================
// helpers
// ===========================================================================
__device__ __forceinline__ uint32_t smem_u32(const void* p) {
    uint32_t a;
    asm("{ .reg .u64 t; cvta.to.shared.u64 t, %1; cvt.u32.u64 %0, t; }"
        : "=r"(a) : "l"(p));
    return a;
}

__device__ __forceinline__ void cp_async16(uint32_t saddr, const void* gaddr) {
    asm volatile("cp.async.cg.shared.global [%0], [%1], 16;"
                 :: "r"(saddr), "l"(gaddr));
}

__device__ __forceinline__ void ldm4(uint32_t* r, uint32_t addr) {
    asm volatile("ldmatrix.sync.aligned.m8n8.x4.shared.b16 {%0,%1,%2,%3}, [%4];"
                 : "=r"(r[0]), "=r"(r[1]), "=r"(r[2]), "=r"(r[3]) : "r"(addr));
}

__device__ __forceinline__ void mma_bf16(float* d, const uint32_t* a,
                                         const uint32_t* b) {
    asm volatile(
        "mma.sync.aligned.m16n8k16.row.col.f32.bf16.bf16.f32 "
        "{%0,%1,%2,%3}, {%4,%5,%6,%7}, {%8,%9}, {%0,%1,%2,%3};"
        : "+f"(d[0]), "+f"(d[1]), "+f"(d[2]), "+f"(d[3])
        : "r"(a[0]), "r"(a[1]), "r"(a[2]), "r"(a[3]), "r"(b[0]), "r"(b[1]));
}

// ===========================================================================
// f32 -> (bf16 hi, bf16 lo) splitter.  total elems divisible by 4*256*grid.
// ===========================================================================
__global__ void split_bf16(const float* __restrict__ in,
                           __nv_bfloat16* __restrict__ hi,
                           __nv_bfloat16* __restrict__ lo) {
    const int i = blockIdx.x * blockDim.x + threadIdx.x;
    float4 v = ((const float4*)in)[i];
    __nv_bfloat16 h0 = __float2bfloat16(v.x);
    __nv_bfloat16 h1 = __float2bfloat16(v.y);
    __nv_bfloat16 h2 = __float2bfloat16(v.z);
    __nv_bfloat16 h3 = __float2bfloat16(v.w);
    __nv_bfloat16 l0 = __float2bfloat16(v.x - __bfloat162float(h0));
    __nv_bfloat16 l1 = __float2bfloat16(v.y - __bfloat162float(h1));
    __nv_bfloat16 l2 = __float2bfloat16(v.z - __bfloat162float(h2));
    __nv_bfloat16 l3 = __float2bfloat16(v.w - __bfloat162float(h3));
    ((__nv_bfloat162*)hi)[2 * i]     = __halves2bfloat162(h0, h1);
    ((__nv_bfloat162*)hi)[2 * i + 1] = __halves2bfloat162(h2, h3);
    ((__nv_bfloat162*)lo)[2 * i]     = __halves2bfloat162(l0, l1);
    ((__nv_bfloat162*)lo)[2 * i + 1] = __halves2bfloat162(l2, l3);
}

// ===========================================================================
// bf16x3 tensor-core GEMM (NT): C[m][n] = sum_k A[m][k]*B[n][k] + bias[n]
//   A = Ahi + Alo, B = Bhi + Blo; D += AhBh + AhBl + AlBh   (fp32 accum)
// BM=BN=128, BK=32, 256 thr (8 warps: warp tile 64x32).
// 2-stage cp.async pipeline, 80 KB smem -> 2 CTAs/SM (occupancy fix, R7:
// tensor=49% @ occ=12% was the binder). launch_bounds(256,2) caps regs at 128.
// smem rows padded to 80B (stride 5 quad-banks -> conflict-free ldmatrix).
// ===========================================================================
#define PB      10240                // plane bytes: 128 rows * 80B
#define STAGE_B (4 * PB)             // Ahi,Alo,Bhi,Blo
#define STAGES  2
#define GEMM_SMEM (STAGES * STAGE_B) // 81920

__global__ void __launch_bounds__(256, 2) gemm_bf16x3(
    const __nv_bfloat16* __restrict__ Ah, const __nv_bfloat16* __restrict__ Al,
    const __nv_bfloat16* __restrict__ Bh, const __nv_bfloat16* __restrict__ Bl,
    const float* __restrict__ bias, float* __restrict__ C,
    int M, int N, int K)
{
    extern __shared__ char smem[];
    const uint32_t sb = smem_u32(smem);
    const int tid    = threadIdx.x;
    const int lane   = tid & 31;
    const int wid    = tid >> 5;
    const int warp_m = wid & 1;
    const int warp_n = wid >> 1;
    const int bm     = blockIdx.y << 7;
    const int bn     = blockIdx.x << 7;

    // ---- cp.async mapping: 8 x 16B per thread per stage ----
    uint32_t s_off[8];
    const __nv_bfloat16* g_ptr[8];
#pragma unroll
    for (int i = 0; i < 8; i++) {
        const int c   = tid + (i << 8);     // 0..2047
        const int p   = c >> 9;             // plane
        const int q   = c & 511;
        const int row = q >> 2;
        const int seg = q & 3;
        s_off[i] = p * PB + row * 80 + seg * 16;
        const __nv_bfloat16* base =
            (p == 0) ? Ah + (size_t)(bm + row) * K :
            (p == 1) ? Al + (size_t)(bm + row) * K :
            (p == 2) ? Bh + (size_t)(bn + row) * K :
                       Bl + (size_t)(bn + row) * K;
        g_ptr[i] = base + seg * 8;
    }

    auto issue = [&](int s, int t) {
        const uint32_t sbase = sb + s * STAGE_B;
#pragma unroll
        for (int i = 0; i < 8; i++)
            cp_async16(sbase + s_off[i], g_ptr[i] + t * 32);
        asm volatile("cp.async.commit_group;");
    };

    float d[4][4][4];
#pragma unroll
    for (int mi = 0; mi < 4; mi++)
#pragma unroll
        for (int ni = 0; ni < 4; ni++)
#pragma unroll
            for (int j = 0; j < 4; j++) d[mi][ni][j] = 0.f;

    // per-lane ldmatrix bases (bytes within plane)
    const uint32_t a_base = (warp_m * 64 + (lane & 15)) * 80 + (lane >> 4) * 16;
    const uint32_t b_base = (warp_n * 32 + (lane & 7) + ((lane >> 4) & 1) * 8) * 80
                          + ((lane >> 3) & 1) * 16;

    const int nchunk = K >> 5;
    issue(0, 0);

    for (int t = 0; t < nchunk; t++) {
        // prefetch next chunk into the other buffer (freed by sync of t-1)
        if (t + 1 < nchunk) {
            issue((t + 1) & 1, t + 1);
            asm volatile("cp.async.wait_group 1;");
        } else {
            asm volatile("cp.async.wait_group 0;");
        }
        __syncthreads();

        const uint32_t st = sb + (t & 1) * STAGE_B;
        const uint32_t aH = st, aL = st + PB, bH = st + 2 * PB, bL = st + 3 * PB;
#pragma unroll
        for (int ks = 0; ks < 2; ks++) {
            uint32_t ah[4][4], al[4][4], bh[4][2], bl[4][2];
            const uint32_t ka = a_base + ks * 32;
            const uint32_t kb = b_base + ks * 32;
#pragma unroll
            for (int mi = 0; mi < 4; mi++) {
                ldm4(ah[mi], aH + ka + mi * 1280);
                ldm4(al[mi], aL + ka + mi * 1280);
            }
#pragma unroll
            for (int nj = 0; nj < 2; nj++) {
                uint32_t r[4];
                ldm4(r, bH + kb + nj * 1280);
                bh[2*nj][0] = r[0]; bh[2*nj][1] = r[1];
                bh[2*nj+1][0] = r[2]; bh[2*nj+1][1] = r[3];
                ldm4(r, bL + kb + nj * 1280);
                bl[2*nj][0] = r[0]; bl[2*nj][1] = r[1];
                bl[2*nj+1][0] = r[2]; bl[2*nj+1][1] = r[3];
            }
#pragma unroll
            for (int mi = 0; mi < 4; mi++)
#pragma unroll
                for (int ni = 0; ni < 4; ni++) {
                    mma_bf16(d[mi][ni], ah[mi], bh[ni]);
                    mma_bf16(d[mi][ni], ah[mi], bl[ni]);
                    mma_bf16(d[mi][ni], al[mi], bh[ni]);
                }
        }
        __syncthreads();
    }

    // ---- epilogue ----
#pragma unroll
    for (int ni = 0; ni < 4; ni++) {
        const int cn = bn + warp_n * 32 + ni * 8 + 2 * (lane & 3);
        const float b0 = bias[cn], b1 = bias[cn + 1];
#pragma unroll
        for (int mi = 0; mi < 4; mi++) {
            const int r0 = bm + warp_m * 64 + mi * 16 + (lane >> 2);
            float2 v0 = make_float2(d[mi][ni][0] + b0, d[mi][ni][1] + b1);
            float2 v1 = make_float2(d[mi][ni][2] + b0, d[mi][ni][3] + b1);
            *(float2*)(C + (size_t)r0 * N + cn)       = v0;
            *(float2*)(C + (size_t)(r0 + 8) * N + cn) = v1;
        }
    }
}

// ---------------------------------------------------------------------------
// Fused block attention (unchanged math); output emitted as bf16 hi/lo.
// ---------------------------------------------------------------------------
#define SMEM_FLOATS (4160 + 65*68 + 4160 + 4225 + 4225 + 4*4*68)

__global__ void __launch_bounds__(128) attn_kernel(
    const float* __restrict__ qkv, const int* __restrict__ mask,
    const float* __restrict__ edge, const float* __restrict__ gate_w,
    const float* __restrict__ gate_b,
    __nv_bfloat16* __restrict__ ohi, __nv_bfloat16* __restrict__ olo)
{
    extern __shared__ float sm[];
    float* sQ  = sm;
    float* sK  = sm + 4160;
    float* sV  = sm + 4160 + 4420;
    float* sB3 = sm + 4160 + 4420 + 4160;
    float* sG  = sB3 + 4225;
    float* sS  = sG + 4225;

    const int blk  = blockIdx.x >> 3;
    const int h    = blockIdx.x & 7;
    const int tid  = threadIdx.x;
    const int lane = tid & 31;
    const int warp = tid >> 5;

    const float* qb = qkv + (size_t)blk * (LQ * 1536) + h * 64;
    for (int i = tid; i < LQ * 16; i += 128) {
        int l = i >> 4, c = (i & 15) << 2;
        const float* p = qb + (size_t)l * 1536 + c;
        float4 qv = *(const float4*)(p);
        float4 kv = *(const float4*)(p + 512);
        float4 vv = *(const float4*)(p + 1024);
        *(float4*)(sQ + l * 64 + c) = qv;
        sK[l * 68 + c + 0] = kv.x; sK[l * 68 + c + 1] = kv.y;
        sK[l * 68 + c + 2] = kv.z; sK[l * 68 + c + 3] = kv.w;
        *(float4*)(sV + l * 64 + c) = vv;
    }

    const float gw0 = gate_w[h * 4 + 0], gw1 = gate_w[h * 4 + 1];
    const float gw2 = gate_w[h * 4 + 2], gw3 = gate_w[h * 4 + 3];
    const float gb  = gate_b[h];
    const float* eb = edge + (size_t)blk * (LQ * LQ * 4);
    const int*   mb = mask + (size_t)blk * (LQ * LQ);
    for (int i = tid; i < LQ * LQ; i += 128) {
        int qr = i / 65, kc = i - qr * 65;
        float4 e = *(const float4*)(eb + (size_t)i * 4);
        if (qr == kc && qr < 64) { e.x = 0.f; e.y = 0.f; e.z = 0.f; e.w = 1.f; }
        float g  = e.x * gw0 + e.y * gw1 + e.z * gw2 + e.w * gw3 + gb;
        float b3 = e.w;
        if (mb[i] == 0) { g = 0.f; b3 = -1e30f; }
        sB3[i] = b3;
        sG[i]  = g;
    }
    __syncthreads();

    float* myS = sS + warp * (4 * 68);

    for (int base = warp * 4; base < 65; base += 16) {
        const int nr = (65 - base) < 4 ? (65 - base) : 4;
        const float* q0 = sQ + base * 64;

        float acc0[4] = {0.f, 0.f, 0.f, 0.f};
        float acc1[4] = {0.f, 0.f, 0.f, 0.f};
        const float* kr1 = sK + lane * 68;
        const float* kr2 = sK + (lane + 32) * 68;
#pragma unroll
        for (int d = 0; d < 64; d += 4) {
            float4 k1 = *(const float4*)(kr1 + d);
            float4 k2 = *(const float4*)(kr2 + d);
#pragma unroll
            for (int i = 0; i < 4; i++) {
                float4 qv = *(const float4*)(q0 + i * 64 + d);
                acc0[i] += qv.x * k1.x + qv.y * k1.y + qv.z * k1.z + qv.w * k1.w;
                acc1[i] += qv.x * k2.x + qv.y * k2.y + qv.z * k2.z + qv.w * k2.w;
            }
        }
        float s64[4];
        {
            const float* k64 = sK + 64 * 68;
            float ka = k64[lane], kb = k64[lane + 32];
#pragma unroll
            for (int i = 0; i < 4; i++) {
                float p = q0[i * 64 + lane] * ka + q0[i * 64 + lane + 32] * kb;
#pragma unroll
                for (int o = 16; o; o >>= 1) p += __shfl_xor_sync(0xffffffffu, p, o);
                s64[i] = p;
            }
        }

#pragma unroll
        for (int i = 0; i < 4; i++) {
            if (i >= nr) break;
            const int r = base + i;
            const float* brow = sB3 + r * 65;
            const float* grow = sG  + r * 65;
            float sc0 = acc0[i] * SCALE_F + brow[lane];
            float sc1 = acc1[i] * SCALE_F + brow[lane + 32];
            float sc2 = s64[i]  * SCALE_F + brow[64];
            float m = fmaxf(sc2, fmaxf(sc0, sc1));
#pragma unroll
            for (int o = 16; o; o >>= 1) m = fmaxf(m, __shfl_xor_sync(0xffffffffu, m, o));
            float p0 = __expf(sc0 - m), p1 = __expf(sc1 - m), p2 = __expf(sc2 - m);
            float s = p0 + p1;
#pragma unroll
            for (int o = 16; o; o >>= 1) s += __shfl_xor_sync(0xffffffffu, s, o);
            float inv = 1.f / (s + p2);
            myS[i * 68 + lane]      = p0 * inv + grow[lane];
            myS[i * 68 + lane + 32] = p1 * inv + grow[lane + 32];
            if (lane == 0) myS[i * 68 + 64] = p2 * inv + grow[64];
        }
        __syncwarp();

        float o0[4] = {0.f, 0.f, 0.f, 0.f};
        float o1[4] = {0.f, 0.f, 0.f, 0.f};
        for (int k = 0; k < 65; k++) {
            float v0 = sV[k * 64 + lane];
            float v1 = sV[k * 64 + lane + 32];
#pragma unroll
            for (int i = 0; i < 4; i++) {
                float c = myS[i * 68 + k];
                o0[i] += c * v0;
                o1[i] += c * v1;
            }
        }
#pragma unroll
        for (int i = 0; i < 4; i++) {
            if (i < nr) {
                const size_t idx = ((size_t)(blk * 65 + base + i)) * 512 + h * 64;
                float va = o0[i], vb = o1[i];
                __nv_bfloat16 ha = __float2bfloat16(va);
                __nv_bfloat16 hb = __float2bfloat16(vb);
                ohi[idx + lane]      = ha;
                ohi[idx + lane + 32] = hb;
                olo[idx + lane]      = __float2bfloat16(va - __bfloat162float(ha));
                olo[idx + lane + 32] = __float2bfloat16(vb - __bfloat162float(hb));
            }
        }
        __syncwarp();
    }
}

// ---------------------------------------------------------------------------
extern "C" void kernel_launch(void* const* d_in, const int* in_sizes, int n_in,
                              void* d_out, int out_size)
{
    const float* x         = (const float*)d_in[0];
    const int*   attn_mask = (const int*)  d_in[1];
    const float* edge      = (const float*)d_in[2];
    const float* qkv_w     = (const float*)d_in[3];
    const float* qkv_b     = (const float*)d_in[4];
    const float* proj_w    = (const float*)d_in[5];
    const float* proj_b    = (const float*)d_in[6];
    const float* gate_w    = (const float*)d_in[7];
    const float* gate_b    = (const float*)d_in[8];
    float* out = (float*)d_out;

    float *qkv = nullptr;
    __nv_bfloat16 *xhi, *xlo, *wqhi, *wqlo, *wphi, *wplo, *ahi, *alo;
    cudaGetSymbolAddress((void**)&qkv,  g_qkv);
    cudaGetSymbolAddress((void**)&xhi,  g_xhi);
    cudaGetSymbolAddress((void**)&xlo,  g_xlo);
    cudaGetSymbolAddress((void**)&wqhi, g_wqhi);
    cudaGetSymbolAddress((void**)&wqlo, g_wqlo);
    cudaGetSymbolAddress((void**)&wphi, g_wphi);
    cudaGetSymbolAddress((void**)&wplo, g_wplo);
    cudaGetSymbolAddress((void**)&ahi,  g_ahi);
    cudaGetSymbolAddress((void**)&alo,  g_alo);

    cudaFuncSetAttribute(gemm_bf16x3,
                         cudaFuncAttributeMaxDynamicSharedMemorySize, GEMM_SMEM);
    const int attn_smem = SMEM_FLOATS * (int)sizeof(float);
    cudaFuncSetAttribute(attn_kernel,
                         cudaFuncAttributeMaxDynamicSharedMemorySize, attn_smem);

    // 0) split inputs/weights into bf16 hi/lo planes
    split_bf16<<<(NTOK * 512) / 1024, 256>>>(x, xhi, xlo);
    split_bf16<<<(1536 * 512) / 1024, 256>>>(qkv_w, wqhi, wqlo);
    split_bf16<<<(512 * 512) / 1024, 256>>>(proj_w, wphi, wplo);

    // 1) QKV projection (bf16x3 tensor cores)
    dim3 g1(1536 / 128, NTOK / 128);
    gemm_bf16x3<<<g1, 256, GEMM_SMEM>>>(xhi, xlo, wqhi, wqlo, qkv_b, qkv,
                                        NTOK, 1536, 512);

    // 2) Fused block attention (f32 in, bf16 hi/lo out)
    attn_kernel<<<NBLK * HH, 128, attn_smem>>>(qkv, attn_mask, edge,
                                               gate_w, gate_b, ahi, alo);

    // 3) Output projection (bf16x3 tensor cores)
    dim3 g2(512 / 128, NTOK / 128);
    gemm_bf16x3<<<g2, 256, GEMM_SMEM>>>(ahi, alo, wphi, wplo, proj_b, out,
                                        NTOK, 512, 512);
}

// round 11
// speedup vs baseline: 1.9196x; 1.0281x over previous
#include <cuda_runtime.h>
#include <cuda_bf16.h>
#include <cstddef>
#include <cstdint>

// Problem constants
#define BB    4
#define NBB   128
#define LQ    65
#define HH    8
#define HD    64
#define CC    512
#define NTOK  (BB * NBB * LQ)        // 33280
#define NBLK  (BB * NBB)             // 512
#define SCALE_F 0.125f               // HD^-0.5

// Scratch (no cudaMalloc allowed)
__device__ float         g_qkv[(size_t)NTOK * 1536];
__device__ __nv_bfloat16 g_xhi[(size_t)NTOK * 512];
__device__ __nv_bfloat16 g_xlo[(size_t)NTOK * 512];
__device__ __nv_bfloat16 g_wqhi[1536 * 512];
__device__ __nv_bfloat16 g_wqlo[1536 * 512];
__device__ __nv_bfloat16 g_wphi[512 * 512];
__device__ __nv_bfloat16 g_wplo[512 * 512];
__device__ __nv_bfloat16 g_ahi[(size_t)NTOK * 512];
__device__ __nv_bfloat16 g_alo[(size_t)NTOK * 512];

// ===========================================================================
// helpers
// ===========================================================================
__device__ __forceinline__ uint32_t smem_u32(const void* p) {
    uint32_t a;
    asm("{ .reg .u64 t; cvta.to.shared.u64 t, %1; cvt.u32.u64 %0, t; }"
        : "=r"(a) : "l"(p));
    return a;
}

__device__ __forceinline__ void cp_async16(uint32_t saddr, const void* gaddr) {
    asm volatile("cp.async.cg.shared.global [%0], [%1], 16;"
                 :: "r"(saddr), "l"(gaddr));
}

__device__ __forceinline__ void ldm4(uint32_t* r, uint32_t addr) {
    asm volatile("ldmatrix.sync.aligned.m8n8.x4.shared.b16 {%0,%1,%2,%3}, [%4];"
                 : "=r"(r[0]), "=r"(r[1]), "=r"(r[2]), "=r"(r[3]) : "r"(addr));
}

__device__ __forceinline__ void mma_bf16(float* d, const uint32_t* a,
                                         const uint32_t* b) {
    asm volatile(
        "mma.sync.aligned.m16n8k16.row.col.f32.bf16.bf16.f32 "
        "{%0,%1,%2,%3}, {%4,%5,%6,%7}, {%8,%9}, {%0,%1,%2,%3};"
        : "+f"(d[0]), "+f"(d[1]), "+f"(d[2]), "+f"(d[3])
        : "r"(a[0]), "r"(a[1]), "r"(a[2]), "r"(a[3]), "r"(b[0]), "r"(b[1]));
}

// ===========================================================================
// f32 -> (bf16 hi, bf16 lo) splitter
// ===========================================================================
__global__ void split_bf16(const float* __restrict__ in,
                           __nv_bfloat16* __restrict__ hi,
                           __nv_bfloat16* __restrict__ lo) {
    const int i = blockIdx.x * blockDim.x + threadIdx.x;
    float4 v = ((const float4*)in)[i];
    __nv_bfloat16 h0 = __float2bfloat16(v.x);
    __nv_bfloat16 h1 = __float2bfloat16(v.y);
    __nv_bfloat16 h2 = __float2bfloat16(v.z);
    __nv_bfloat16 h3 = __float2bfloat16(v.w);
    __nv_bfloat16 l0 = __float2bfloat16(v.x - __bfloat162float(h0));
    __nv_bfloat16 l1 = __float2bfloat16(v.y - __bfloat162float(h1));
    __nv_bfloat16 l2 = __float2bfloat16(v.z - __bfloat162float(h2));
    __nv_bfloat16 l3 = __float2bfloat16(v.w - __bfloat162float(h3));
    ((__nv_bfloat162*)hi)[2 * i]     = __halves2bfloat162(h0, h1);
    ((__nv_bfloat162*)hi)[2 * i + 1] = __halves2bfloat162(h2, h3);
    ((__nv_bfloat162*)lo)[2 * i]     = __halves2bfloat162(l0, l1);
    ((__nv_bfloat162*)lo)[2 * i + 1] = __halves2bfloat162(l2, l3);
}

// ===========================================================================
// bf16x3 tensor-core GEMM (NT). 2-stage cp.async, ONE barrier per k-chunk
// (R9: tensor=60% @ two barriers/chunk; leading sync alone orders
// compute(t-1) vs refill of its buffer, trailing sync removed).
// ===========================================================================
#define PB      10240
#define STAGE_B (4 * PB)
#define STAGES  2
#define GEMM_SMEM (STAGES * STAGE_B)

__global__ void __launch_bounds__(256, 2) gemm_bf16x3(
    const __nv_bfloat16* __restrict__ Ah, const __nv_bfloat16* __restrict__ Al,
    const __nv_bfloat16* __restrict__ Bh, const __nv_bfloat16* __restrict__ Bl,
    const float* __restrict__ bias, float* __restrict__ C,
    int M, int N, int K)
{
    extern __shared__ char smem[];
    const uint32_t sb = smem_u32(smem);
    const int tid    = threadIdx.x;
    const int lane   = tid & 31;
    const int wid    = tid >> 5;
    const int warp_m = wid & 1;
    const int warp_n = wid >> 1;
    const int bm     = blockIdx.y << 7;
    const int bn     = blockIdx.x << 7;

    uint32_t s_off[8];
    const __nv_bfloat16* g_ptr[8];
#pragma unroll
    for (int i = 0; i < 8; i++) {
        const int c   = tid + (i << 8);
        const int p   = c >> 9;
        const int q   = c & 511;
        const int row = q >> 2;
        const int seg = q & 3;
        s_off[i] = p * PB + row * 80 + seg * 16;
        const __nv_bfloat16* base =
            (p == 0) ? Ah + (size_t)(bm + row) * K :
            (p == 1) ? Al + (size_t)(bm + row) * K :
            (p == 2) ? Bh + (size_t)(bn + row) * K :
                       Bl + (size_t)(bn + row) * K;
        g_ptr[i] = base + seg * 8;
    }

    auto issue = [&](int s, int t) {
        const uint32_t sbase = sb + s * STAGE_B;
#pragma unroll
        for (int i = 0; i < 8; i++)
            cp_async16(sbase + s_off[i], g_ptr[i] + t * 32);
        asm volatile("cp.async.commit_group;");
    };

    float d[4][4][4];
#pragma unroll
    for (int mi = 0; mi < 4; mi++)
#pragma unroll
        for (int ni = 0; ni < 4; ni++)
#pragma unroll
            for (int j = 0; j < 4; j++) d[mi][ni][j] = 0.f;

    const uint32_t a_base = (warp_m * 64 + (lane & 15)) * 80 + (lane >> 4) * 16;
    const uint32_t b_base = (warp_n * 32 + (lane & 7) + ((lane >> 4) & 1) * 8) * 80
                          + ((lane >> 3) & 1) * 16;

    const int nchunk = K >> 5;
    issue(0, 0);

    for (int t = 0; t < nchunk; t++) {
        asm volatile("cp.async.wait_group 0;");
        __syncthreads();           // data visible + orders compute(t-1) vs refill
        if (t + 1 < nchunk) issue((t + 1) & 1, t + 1);

        const uint32_t st = sb + (t & 1) * STAGE_B;
        const uint32_t aH = st, aL = st + PB, bH = st + 2 * PB, bL = st + 3 * PB;
#pragma unroll
        for (int ks = 0; ks < 2; ks++) {
            uint32_t ah[4][4], al[4][4], bh[4][2], bl[4][2];
            const uint32_t ka = a_base + ks * 32;
            const uint32_t kb = b_base + ks * 32;
#pragma unroll
            for (int mi = 0; mi < 4; mi++) {
                ldm4(ah[mi], aH + ka + mi * 1280);
                ldm4(al[mi], aL + ka + mi * 1280);
            }
#pragma unroll
            for (int nj = 0; nj < 2; nj++) {
                uint32_t r[4];
                ldm4(r, bH + kb + nj * 1280);
                bh[2*nj][0] = r[0]; bh[2*nj][1] = r[1];
                bh[2*nj+1][0] = r[2]; bh[2*nj+1][1] = r[3];
                ldm4(r, bL + kb + nj * 1280);
                bl[2*nj][0] = r[0]; bl[2*nj][1] = r[1];
                bl[2*nj+1][0] = r[2]; bl[2*nj+1][1] = r[3];
            }
#pragma unroll
            for (int mi = 0; mi < 4; mi++)
#pragma unroll
                for (int ni = 0; ni < 4; ni++) {
                    mma_bf16(d[mi][ni], ah[mi], bh[ni]);
                    mma_bf16(d[mi][ni], ah[mi], bl[ni]);
                    mma_bf16(d[mi][ni], al[mi], bh[ni]);
                }
        }
    }

#pragma unroll
    for (int ni = 0; ni < 4; ni++) {
        const int cn = bn + warp_n * 32 + ni * 8 + 2 * (lane & 3);
        const float b0 = bias[cn], b1 = bias[cn + 1];
#pragma unroll
        for (int mi = 0; mi < 4; mi++) {
            const int r0 = bm + warp_m * 64 + mi * 16 + (lane >> 2);
            float2 v0 = make_float2(d[mi][ni][0] + b0, d[mi][ni][1] + b1);
            float2 v1 = make_float2(d[mi][ni][2] + b0, d[mi][ni][3] + b1);
            *(float2*)(C + (size_t)r0 * N + cn)       = v0;
            *(float2*)(C + (size_t)(r0 + 8) * N + cn) = v1;
        }
    }
}

// ---------------------------------------------------------------------------
// Fused block attention, R=16 row blocking.
// Warp w handles rows [16w, 16w+16); warp 3 additionally handles row 64.
// K/V smem re-reads drop 17/5 ~ 3.4x vs R=4. Scale folded into staged Q.
// smem: Q 4160 | K 4420 | V 4160 | B3 4225 | G 4225 | S 4*16*68+68
// ---------------------------------------------------------------------------
#define SMEM_FLOATS (4160 + 4420 + 4160 + 4225 + 4225 + (4*16*68 + 68))

__global__ void __launch_bounds__(128) attn_kernel(
    const float* __restrict__ qkv, const int* __restrict__ mask,
    const float* __restrict__ edge, const float* __restrict__ gate_w,
    const float* __restrict__ gate_b,
    __nv_bfloat16* __restrict__ ohi, __nv_bfloat16* __restrict__ olo)
{
    extern __shared__ float sm[];
    float* sQ  = sm;                       // 4160 (pre-scaled by SCALE_F)
    float* sK  = sm + 4160;                // 4420 (stride 68)
    float* sV  = sm + 8580;                // 4160
    float* sB3 = sm + 12740;               // 4225
    float* sG  = sm + 16965;               // 4225
    float* sS  = sm + 21190;               // 4*16*68 + 68

    const int blk  = blockIdx.x >> 3;
    const int h    = blockIdx.x & 7;
    const int tid  = threadIdx.x;
    const int lane = tid & 31;
    const int warp = tid >> 5;

    // ---- stage Q(*scale)/K/V ----
    const float* qb = qkv + (size_t)blk * (LQ * 1536) + h * 64;
    for (int i = tid; i < LQ * 16; i += 128) {
        int l = i >> 4, c = (i & 15) << 2;
        const float* p = qb + (size_t)l * 1536 + c;
        float4 qv = *(const float4*)(p);
        float4 kv = *(const float4*)(p + 512);
        float4 vv = *(const float4*)(p + 1024);
        qv.x *= SCALE_F; qv.y *= SCALE_F; qv.z *= SCALE_F; qv.w *= SCALE_F;
        *(float4*)(sQ + l * 64 + c) = qv;
        sK[l * 68 + c + 0] = kv.x; sK[l * 68 + c + 1] = kv.y;
        sK[l * 68 + c + 2] = kv.z; sK[l * 68 + c + 3] = kv.w;
        *(float4*)(sV + l * 64 + c) = vv;
    }

    // ---- stage bias3 / gate ----
    const float gw0 = gate_w[h * 4 + 0], gw1 = gate_w[h * 4 + 1];
    const float gw2 = gate_w[h * 4 + 2], gw3 = gate_w[h * 4 + 3];
    const float gb  = gate_b[h];
    const float* eb = edge + (size_t)blk * (LQ * LQ * 4);
    const int*   mb = mask + (size_t)blk * (LQ * LQ);
    for (int i = tid; i < LQ * LQ; i += 128) {
        int qr = i / 65, kc = i - qr * 65;
        float4 e = *(const float4*)(eb + (size_t)i * 4);
        if (qr == kc && qr < 64) { e.x = 0.f; e.y = 0.f; e.z = 0.f; e.w = 1.f; }
        float g  = e.x * gw0 + e.y * gw1 + e.z * gw2 + e.w * gw3 + gb;
        float b3 = e.w;
        if (mb[i] == 0) { g = 0.f; b3 = -1e30f; }
        sB3[i] = b3;
        sG[i]  = g;
    }
    __syncthreads();

    const float* kr1 = sK + lane * 68;
    const float* kr2 = sK + (lane + 32) * 68;
    const float  ka  = sK[64 * 68 + lane];
    const float  kb  = sK[64 * 68 + lane + 32];

    // ===== main group: rows [16*warp, 16*warp+16) — always full =====
    {
        const int base = warp * 16;
        const float* q0 = sQ + base * 64;

        float acc0[16], acc1[16];
#pragma unroll
        for (int i = 0; i < 16; i++) { acc0[i] = 0.f; acc1[i] = 0.f; }

#pragma unroll
        for (int d = 0; d < 64; d += 4) {
            float4 k1 = *(const float4*)(kr1 + d);
            float4 k2 = *(const float4*)(kr2 + d);
#pragma unroll
            for (int i = 0; i < 16; i++) {
                float4 qv = *(const float4*)(q0 + i * 64 + d);   // broadcast
                acc0[i] += qv.x * k1.x + qv.y * k1.y + qv.z * k1.z + qv.w * k1.w;
                acc1[i] += qv.x * k2.x + qv.y * k2.y + qv.z * k2.z + qv.w * k2.w;
            }
        }
        // key 64 via cross-lane reduction
        float s64[16];
#pragma unroll
        for (int i = 0; i < 16; i++) {
            float p = q0[i * 64 + lane] * ka + q0[i * 64 + lane + 32] * kb;
#pragma unroll
            for (int o = 16; o; o >>= 1) p += __shfl_xor_sync(0xffffffffu, p, o);
            s64[i] = p;
        }

        float* myS = sS + warp * (16 * 68);
#pragma unroll
        for (int i = 0; i < 16; i++) {
            const int r = base + i;
            const float* brow = sB3 + r * 65;
            const float* grow = sG  + r * 65;
            float sc0 = acc0[i] + brow[lane];
            float sc1 = acc1[i] + brow[lane + 32];
            float sc2 = s64[i]  + brow[64];
            float m = fmaxf(sc2, fmaxf(sc0, sc1));
#pragma unroll
            for (int o = 16; o; o >>= 1) m = fmaxf(m, __shfl_xor_sync(0xffffffffu, m, o));
            float p0 = __expf(sc0 - m), p1 = __expf(sc1 - m), p2 = __expf(sc2 - m);
            float s = p0 + p1;
#pragma unroll
            for (int o = 16; o; o >>= 1) s += __shfl_xor_sync(0xffffffffu, s, o);
            float inv = 1.f / (s + p2);
            myS[i * 68 + lane]      = p0 * inv + grow[lane];
            myS[i * 68 + lane + 32] = p1 * inv + grow[lane + 32];
            if (lane == 0) myS[i * 68 + 64] = p2 * inv + grow[64];
        }
        __syncwarp();

        float o0[16], o1[16];
#pragma unroll
        for (int i = 0; i < 16; i++) { o0[i] = 0.f; o1[i] = 0.f; }
        for (int k = 0; k < 65; k++) {
            float v0 = sV[k * 64 + lane];
            float v1 = sV[k * 64 + lane + 32];
#pragma unroll
            for (int i = 0; i < 16; i++) {
                float c = myS[i * 68 + k];
                o0[i] += c * v0;
                o1[i] += c * v1;
            }
        }
#pragma unroll
        for (int i = 0; i < 16; i++) {
            const size_t idx = ((size_t)(blk * 65 + base + i)) * 512 + h * 64;
            float va = o0[i], vb = o1[i];
            __nv_bfloat16 ha = __float2bfloat16(va);
            __nv_bfloat16 hb = __float2bfloat16(vb);
            ohi[idx + lane]      = ha;
            ohi[idx + lane + 32] = hb;
            olo[idx + lane]      = __float2bfloat16(va - __bfloat162float(ha));
            olo[idx + lane + 32] = __float2bfloat16(vb - __bfloat162float(hb));
        }
    }

    // ===== row 64 (warp 3 only) =====
    if (warp == 3) {
        const float* q64 = sQ + 64 * 64;
        float a0 = 0.f, a1 = 0.f;
#pragma unroll
        for (int d = 0; d < 64; d += 4) {
            float4 k1 = *(const float4*)(kr1 + d);
            float4 k2 = *(const float4*)(kr2 + d);
            float4 qv = *(const float4*)(q64 + d);
            a0 += qv.x * k1.x + qv.y * k1.y + qv.z * k1.z + qv.w * k1.w;
            a1 += qv.x * k2.x + qv.y * k2.y + qv.z * k2.z + qv.w * k2.w;
        }
        float p = q64[lane] * ka + q64[lane + 32] * kb;
#pragma unroll
        for (int o = 16; o; o >>= 1) p += __shfl_xor_sync(0xffffffffu, p, o);

        const float* brow = sB3 + 64 * 65;
        const float* grow = sG  + 64 * 65;
        float sc0 = a0 + brow[lane];
        float sc1 = a1 + brow[lane + 32];
        float sc2 = p  + brow[64];
        float m = fmaxf(sc2, fmaxf(sc0, sc1));
#pragma unroll
        for (int o = 16; o; o >>= 1) m = fmaxf(m, __shfl_xor_sync(0xffffffffu, m, o));
        float p0 = __expf(sc0 - m), p1 = __expf(sc1 - m), p2 = __expf(sc2 - m);
        float s = p0 + p1;
#pragma unroll
        for (int o = 16; o; o >>= 1) s += __shfl_xor_sync(0xffffffffu, s, o);
        float inv = 1.f / (s + p2);
        float* myS = sS + 4 * 16 * 68;
        myS[lane]      = p0 * inv + grow[lane];
        myS[lane + 32] = p1 * inv + grow[lane + 32];
        if (lane == 0) myS[64] = p2 * inv + grow[64];
        __syncwarp();

        float o0 = 0.f, o1 = 0.f;
        for (int k = 0; k < 65; k++) {
            float c = myS[k];
            o0 += c * sV[k * 64 + lane];
            o1 += c * sV[k * 64 + lane + 32];
        }
        const size_t idx = ((size_t)(blk * 65 + 64)) * 512 + h * 64;
        __nv_bfloat16 ha = __float2bfloat16(o0);
        __nv_bfloat16 hb = __float2bfloat16(o1);
        ohi[idx + lane]      = ha;
        ohi[idx + lane + 32] = hb;
        olo[idx + lane]      = __float2bfloat16(o0 - __bfloat162float(ha));
        olo[idx + lane + 32] = __float2bfloat16(o1 - __bfloat162float(hb));
    }
}

// ---------------------------------------------------------------------------
extern "C" void kernel_launch(void* const* d_in, const int* in_sizes, int n_in,
                              void* d_out, int out_size)
{
    const float* x         = (const float*)d_in[0];
    const int*   attn_mask = (const int*)  d_in[1];
    const float* edge      = (const float*)d_in[2];
    const float* qkv_w     = (const float*)d_in[3];
    const float* qkv_b     = (const float*)d_in[4];
    const float* proj_w    = (const float*)d_in[5];
    const float* proj_b    = (const float*)d_in[6];
    const float* gate_w    = (const float*)d_in[7];
    const float* gate_b    = (const float*)d_in[8];
    float* out = (float*)d_out;

    float *qkv = nullptr;
    __nv_bfloat16 *xhi, *xlo, *wqhi, *wqlo, *wphi, *wplo, *ahi, *alo;
    cudaGetSymbolAddress((void**)&qkv,  g_qkv);
    cudaGetSymbolAddress((void**)&xhi,  g_xhi);
    cudaGetSymbolAddress((void**)&xlo,  g_xlo);
    cudaGetSymbolAddress((void**)&wqhi, g_wqhi);
    cudaGetSymbolAddress((void**)&wqlo, g_wqlo);
    cudaGetSymbolAddress((void**)&wphi, g_wphi);
    cudaGetSymbolAddress((void**)&wplo, g_wplo);
    cudaGetSymbolAddress((void**)&ahi,  g_ahi);
    cudaGetSymbolAddress((void**)&alo,  g_alo);

    cudaFuncSetAttribute(gemm_bf16x3,
                         cudaFuncAttributeMaxDynamicSharedMemorySize, GEMM_SMEM);
    const int attn_smem = SMEM_FLOATS * (int)sizeof(float);
    cudaFuncSetAttribute(attn_kernel,
                         cudaFuncAttributeMaxDynamicSharedMemorySize, attn_smem);

    // 0) split inputs/weights into bf16 hi/lo planes
    split_bf16<<<(NTOK * 512) / 1024, 256>>>(x, xhi, xlo);
    split_bf16<<<(1536 * 512) / 1024, 256>>>(qkv_w, wqhi, wqlo);
    split_bf16<<<(512 * 512) / 1024, 256>>>(proj_w, wphi, wplo);

    // 1) QKV projection (bf16x3 tensor cores)
    dim3 g1(1536 / 128, NTOK / 128);
    gemm_bf16x3<<<g1, 256, GEMM_SMEM>>>(xhi, xlo, wqhi, wqlo, qkv_b, qkv,
                                        NTOK, 1536, 512);

    // 2) Fused block attention (f32 in, bf16 hi/lo out)
    attn_kernel<<<NBLK * HH, 128, attn_smem>>>(qkv, attn_mask, edge,
                                               gate_w, gate_b, ahi, alo);

    // 3) Output projection (bf16x3 tensor cores)
    dim3 g2(512 / 128, NTOK / 128);
    gemm_bf16x3<<<g2, 256, GEMM_SMEM>>>(ahi, alo, wphi, wplo, proj_b, out,
                                        NTOK, 512, 512);
}